// round 10
// baseline (speedup 1.0000x reference)
#include <cuda_runtime.h>
#include <cuda_fp16.h>
#include <cstdint>

#define NJ      55
#define TILE_M  128
#define BLOCK   128
#define GRID_P  592     // 148 SM x 4 blocks

__device__ __forceinline__ uint32_t smem_u32(const void* p) {
    uint32_t a;
    asm("{ .reg .u64 t; cvta.to.shared.u64 t, %1; cvt.u32.u64 %0, t; }" : "=r"(a) : "l"(p));
    return a;
}
__device__ __forceinline__ void ldsm_x4(uint32_t* r, uint32_t addr) {
    asm volatile("ldmatrix.sync.aligned.m8n8.x4.shared.b16 {%0,%1,%2,%3}, [%4];"
                 : "=r"(r[0]), "=r"(r[1]), "=r"(r[2]), "=r"(r[3]) : "r"(addr));
}
__device__ __forceinline__ void mma16816(float* d, const uint32_t* a, uint32_t b0, uint32_t b1) {
    asm volatile("mma.sync.aligned.m16n8k16.row.col.f32.f16.f16.f32 "
                 "{%0,%1,%2,%3}, {%4,%5,%6,%7}, {%8,%9}, {%0,%1,%2,%3};"
                 : "+f"(d[0]), "+f"(d[1]), "+f"(d[2]), "+f"(d[3])
                 : "r"(a[0]), "r"(a[1]), "r"(a[2]), "r"(a[3]), "r"(b0), "r"(b1));
}
__device__ __forceinline__ uint32_t swb(uint32_t b, int r) {
    return (b & 15u) | ((((b >> 4) ^ (uint32_t)(r & 7)) & 7u) << 4);
}
__device__ __forceinline__ void cpa16(uint32_t d, const void* s) {
    asm volatile("cp.async.cg.shared.global [%0], [%1], 16;" :: "r"(d), "l"(s) : "memory");
}
__device__ __forceinline__ void cpa4(uint32_t d, const void* s) {
    asm volatile("cp.async.ca.shared.global [%0], [%1], 4;" :: "r"(d), "l"(s) : "memory");
}
__device__ __forceinline__ uint32_t packh2(float a, float b) {
    __half2 p = __floats2half2_rn(a, b);
    return *(uint32_t*)&p;
}

// stage 16 weight rows (fp32) starting at vertex gv0h into dst
__device__ __forceinline__ void stage_half(const float* __restrict__ weights,
                                           float* dst, long gv0h, long N, int lane)
{
    long remh = N - gv0h;
    uint32_t d = smem_u32(dst);
    if (remh >= 16) {
        const float4* s = (const float4*)(weights + gv0h * NJ);  // 16|gv0h -> 16B aligned
        #pragma unroll 2
        for (int i = lane; i < (16 * NJ) / 4; i += 32)
            cpa16(d + 16u * i, s + i);
    } else if (remh > 0) {
        int nf = (int)remh * NJ;
        int nc = nf >> 2;
        const float4* s = (const float4*)(weights + gv0h * NJ);
        for (int i = lane; i < nc; i += 32) cpa16(d + 16u * i, s + i);
        for (int i = 4 * nc + lane; i < nf; i += 32)
            cpa4(d + 4u * i, weights + gv0h * NJ + i);
    }
}

// stage 32 verts' points (96 floats) starting at vertex gv0 into dst
__device__ __forceinline__ void stage_pts(const float* __restrict__ points,
                                          float* dst, long gv0, long N, int lane)
{
    long rem = N - gv0;
    if (rem > 32) rem = 32;
    if (rem <= 0) return;
    uint32_t d = smem_u32(dst);
    int nf = (int)rem * 3;
    int nc = nf >> 2;
    const float4* s = (const float4*)(points + 3 * gv0);   // 32|gv0 -> 16B aligned
    for (int i = lane; i < nc; i += 32) cpa16(d + 16u * i, s + i);
    for (int i = 4 * nc + lane; i < nf; i += 32)
        cpa4(d + 4u * i, points + 3 * gv0 + i);
}

__global__ __launch_bounds__(BLOCK, 4)
void lbs_hmma_kernel(const float* __restrict__ points,
                     const float* __restrict__ weights,
                     const float* __restrict__ se3,
                     float* __restrict__ out,
                     int N, int n_tiles)
{
    // A tile [128][64] fp16 swizzled; per-half 16-row regions double as D-exchange
    __shared__ __align__(1024) __half s_A[TILE_M * 64];          // 16 KB
    // B build area (hi/lo SE3); after frags hoisted to regs, reused as points bufs
    __shared__ __align__(1024) char  s_BP[4096];                 // 4 KB
    __shared__ __align__(16)   float s_lin[4][32 * NJ];          // 28.16 KB

    const int tid  = threadIdx.x;
    const int wid  = tid >> 5;
    const int lane = tid & 31;

    const uint32_t a_base = smem_u32(s_A);

    // ---- build B (hi/lo split of SE3 rows 0..2, n = r*4+c), load frags, then free ----
    uint32_t BH[4][4], BL[4][4];
    {
        __half* b0 = (__half*)s_BP;               // [16][64]
        __half* b1 = (__half*)(s_BP + 2048);
        for (int idx = tid; idx < 16 * 64; idx += BLOCK) {
            int n = idx >> 6;
            int k = idx & 63;
            float v = (k < NJ && n < 12) ? se3[k * 16 + n] : 0.0f;
            __half hh = __float2half_rn(v);
            __half hl = __float2half_rn(v - __half2float(hh));
            uint32_t off = (uint32_t)(n * 128 + 2 * k);
            off ^= ((off >> 3) & 0x70);
            *(__half*)((char*)b0 + off) = hh;
            *(__half*)((char*)b1 + off) = hl;
        }
        __syncthreads();
        const uint32_t b0b = smem_u32(b0), b1b = smem_u32(b1);
        int nrow = (lane & 7) + (((lane >> 4) & 1) << 3);
        #pragma unroll
        for (int chunk = 0; chunk < 4; chunk++) {
            uint32_t c = (uint32_t)(chunk * 32) + (((uint32_t)(lane >> 3) & 1) << 4);
            uint32_t boff = (uint32_t)nrow * 128 + (c ^ ((uint32_t)(nrow & 7) << 4));
            ldsm_x4(BH[chunk], b0b + boff);
            ldsm_x4(BL[chunk], b1b + boff);
        }
        __syncthreads();   // frags read; s_BP now free for points buffers
    }

    float* slabw = s_lin[wid];
    float* ptsb[2] = { (float*)(s_BP + wid * 768),
                       (float*)(s_BP + wid * 768 + 384) };

    // ---- prologue: prefetch tile0's two halves (+ points) ----
    int tile = blockIdx.x;
    int it = 0;
    if (tile < n_tiles) {
        long gv0 = (long)tile * TILE_M + wid * 32;
        stage_half(weights, slabw, gv0, N, lane);
        stage_pts(points, ptsb[0], gv0, N, lane);
        asm volatile("cp.async.commit_group;" ::: "memory");
        stage_half(weights, slabw + 16 * NJ, gv0 + 16, N, lane);
        asm volatile("cp.async.commit_group;" ::: "memory");
    }

    for (; tile < n_tiles; tile += gridDim.x, it++) {
        const long gv0 = (long)tile * TILE_M + wid * 32;
        const float* ptsw = ptsb[it & 1];

        #pragma unroll
        for (int h = 0; h < 2; h++) {
            // ---- wait oldest group (this half's data) ----
            asm volatile("cp.async.wait_group 1;" ::: "memory");
            __syncwarp();

            // ---- convert: lane pair (rr, side) handles row rr of this half ----
            const int rr = lane & 15;
            const int side = lane >> 4;
            uint32_t hw[16];
            {
                const float* rp = slabw + (h * 16 + rr) * NJ;
                if (!side) {
                    #pragma unroll
                    for (int q = 0; q < 16; q++) hw[q] = packh2(rp[2 * q], rp[2 * q + 1]);
                } else {
                    #pragma unroll
                    for (int q = 0; q < 11; q++) hw[q] = packh2(rp[32 + 2 * q], rp[33 + 2 * q]);
                    hw[11] = packh2(rp[54], 0.0f);
                    hw[12] = hw[13] = hw[14] = hw[15] = 0u;
                }
            }
            __syncwarp();   // all slab reads done before reissue

            // ---- reissue this half-slab for tile+stride (+ points with h0) ----
            {
                long nt = (long)tile + gridDim.x;
                if (nt < n_tiles) {
                    long ngv0 = nt * TILE_M + wid * 32;
                    stage_half(weights, slabw + h * 16 * NJ, ngv0 + 16 * h, N, lane);
                    if (h == 0) stage_pts(points, ptsb[(it + 1) & 1], ngv0, N, lane);
                }
                asm volatile("cp.async.commit_group;" ::: "memory");
            }

            // ---- repack regs -> swizzled A half-tile ----
            {
                const int arow = wid * 32 + h * 16 + rr;
                const uint32_t rowbase = a_base + (uint32_t)arow * 128;
                const uint32_t xr = (uint32_t)(rr & 7) << 4;
                #pragma unroll
                for (int b2 = 0; b2 < 4; b2++) {
                    int b = side * 4 + b2;
                    uint32_t ad = rowbase + (((uint32_t)(b * 16)) ^ xr);
                    asm volatile("st.shared.v4.b32 [%0], {%1,%2,%3,%4};"
                                 :: "r"(ad), "r"(hw[4 * b2 + 0]), "r"(hw[4 * b2 + 1]),
                                    "r"(hw[4 * b2 + 2]), "r"(hw[4 * b2 + 3]) : "memory");
                }
            }
            __syncwarp();

            // ---- MMA: D[16x16] = A_half[16x64] * (Bh + Bl)^T ----
            float d0[4] = {0, 0, 0, 0}, d1[4] = {0, 0, 0, 0};
            #pragma unroll
            for (int chunk = 0; chunk < 4; chunk++) {
                uint32_t a[4];
                int rowa = wid * 32 + h * 16 + rr;
                uint32_t c = (uint32_t)(chunk * 32) + ((uint32_t)side << 4);
                uint32_t ad = a_base + (uint32_t)rowa * 128 + (c ^ ((uint32_t)(rowa & 7) << 4));
                ldsm_x4(a, ad);
                mma16816(d0, a, BH[chunk][0], BH[chunk][1]);
                mma16816(d1, a, BH[chunk][2], BH[chunk][3]);
                mma16816(d0, a, BL[chunk][0], BL[chunk][1]);
                mma16816(d1, a, BL[chunk][2], BL[chunk][3]);
            }

            // ---- D exchange into this half's (dead) A region ----
            char* awarp = (char*)s_A + (wid * 32 + h * 16) * 128;
            {
                int r0 = lane >> 2;
                int cq = 2 * (lane & 3);
                #pragma unroll
                for (int nt = 0; nt < 2; nt++) {
                    float* dd = nt ? d1 : d0;
                    uint32_t cb = (uint32_t)(nt * 8 + cq) * 4;
                    *(float2*)(awarp + r0 * 128 + swb(cb, r0))
                        = make_float2(dd[0], dd[1]);
                    *(float2*)(awarp + (r0 + 8) * 128 + swb(cb, r0 + 8))
                        = make_float2(dd[2], dd[3]);
                }
            }
            __syncwarp();

            // ---- epilogue (lanes 0..15): out = A3x4 * [p;1], points from smem ----
            if (lane < 16) {
                long v = gv0 + h * 16 + lane;
                if (v < N) {
                    float4 q0 = *(float4*)(awarp + lane * 128 + swb(0u,  lane));
                    float4 q1 = *(float4*)(awarp + lane * 128 + swb(16u, lane));
                    float4 q2 = *(float4*)(awarp + lane * 128 + swb(32u, lane));
                    const float* pp = ptsw + 3 * (h * 16 + lane);
                    float px = pp[0], py = pp[1], pz = pp[2];
                    out[3 * v + 0] = fmaf(q0.x, px, fmaf(q0.y, py, fmaf(q0.z, pz, q0.w)));
                    out[3 * v + 1] = fmaf(q1.x, px, fmaf(q1.y, py, fmaf(q1.z, pz, q1.w)));
                    out[3 * v + 2] = fmaf(q2.x, px, fmaf(q2.y, py, fmaf(q2.z, pz, q2.w)));
                }
            }
            __syncwarp();   // exchange reads done before next repack overwrites region
        }
    }
}

extern "C" void kernel_launch(void* const* d_in, const int* in_sizes, int n_in,
                              void* d_out, int out_size)
{
    const int N = out_size / 3;
    const float* points = nullptr;
    const float* weights = nullptr;
    const float* se3 = nullptr;

    for (int i = 0; i < n_in; i++) {
        long sz = in_sizes[i];
        if (sz == (long)NJ * 16)      se3 = (const float*)d_in[i];
        else if (sz == (long)N * NJ)  weights = (const float*)d_in[i];
        else if (sz == (long)N * 3)   points = (const float*)d_in[i];
    }

    int n_tiles = (N + TILE_M - 1) / TILE_M;
    int grid = n_tiles < GRID_P ? n_tiles : GRID_P;
    lbs_hmma_kernel<<<grid, BLOCK>>>(points, weights, se3, (float*)d_out, N, n_tiles);
}

// round 12
// speedup vs baseline: 1.0537x; 1.0537x over previous
#include <cuda_runtime.h>
#include <cuda_fp16.h>
#include <cstdint>

#define NJ      55
#define TILE_M  128
#define BLOCK   128
#define GRID_P  592     // 148 SM x 4 blocks

__device__ __forceinline__ uint32_t smem_u32(const void* p) {
    uint32_t a;
    asm("{ .reg .u64 t; cvta.to.shared.u64 t, %1; cvt.u32.u64 %0, t; }" : "=r"(a) : "l"(p));
    return a;
}
__device__ __forceinline__ void ldsm_x4(uint32_t* r, uint32_t addr) {
    asm volatile("ldmatrix.sync.aligned.m8n8.x4.shared.b16 {%0,%1,%2,%3}, [%4];"
                 : "=r"(r[0]), "=r"(r[1]), "=r"(r[2]), "=r"(r[3]) : "r"(addr));
}
__device__ __forceinline__ void mma16816(float* d, const uint32_t* a, uint32_t b0, uint32_t b1) {
    asm volatile("mma.sync.aligned.m16n8k16.row.col.f32.f16.f16.f32 "
                 "{%0,%1,%2,%3}, {%4,%5,%6,%7}, {%8,%9}, {%0,%1,%2,%3};"
                 : "+f"(d[0]), "+f"(d[1]), "+f"(d[2]), "+f"(d[3])
                 : "r"(a[0]), "r"(a[1]), "r"(a[2]), "r"(a[3]), "r"(b0), "r"(b1));
}
__device__ __forceinline__ uint32_t swb(uint32_t b, int r) {
    return (b & 15u) | ((((b >> 4) ^ (uint32_t)(r & 7)) & 7u) << 4);
}
__device__ __forceinline__ void cpa16(uint32_t d, const void* s) {
    asm volatile("cp.async.cg.shared.global [%0], [%1], 16;" :: "r"(d), "l"(s) : "memory");
}
__device__ __forceinline__ void cpa4(uint32_t d, const void* s) {
    asm volatile("cp.async.ca.shared.global [%0], [%1], 4;" :: "r"(d), "l"(s) : "memory");
}
__device__ __forceinline__ uint32_t packh2(float a, float b) {
    __half2 p = __floats2half2_rn(a, b);
    return *(uint32_t*)&p;
}

// stage one warp's 32 weight rows (raw fp32) + 32 points into smem (one group)
__device__ __forceinline__ void stage_tile(const float* __restrict__ weights,
                                           const float* __restrict__ points,
                                           float* slab, float* pts,
                                           long gv0, long N, int lane)
{
    long rem = N - gv0;
    uint32_t d = smem_u32(slab);
    if (rem >= 32) {
        const float4* s = (const float4*)(weights + gv0 * NJ);  // 32|gv0 -> 16B aligned
        #pragma unroll 2
        for (int i = lane; i < (32 * NJ) / 4; i += 32)
            cpa16(d + 16u * i, s + i);
    } else if (rem > 0) {
        int nf = (int)rem * NJ;
        int nc = nf >> 2;
        const float4* s = (const float4*)(weights + gv0 * NJ);
        for (int i = lane; i < nc; i += 32) cpa16(d + 16u * i, s + i);
        for (int i = 4 * nc + lane; i < nf; i += 32)
            cpa4(d + 4u * i, weights + gv0 * NJ + i);
    }
    // points: 32 verts x 3 floats = 96 floats = 24 float4
    long remp = rem > 32 ? 32 : rem;
    if (remp > 0) {
        uint32_t dp = smem_u32(pts);
        int nf = (int)remp * 3;
        int nc = nf >> 2;
        const float4* s = (const float4*)(points + 3 * gv0);    // 32|gv0 -> 16B aligned
        for (int i = lane; i < nc; i += 32) cpa16(dp + 16u * i, s + i);
        for (int i = 4 * nc + lane; i < nf; i += 32)
            cpa4(dp + 4u * i, points + 3 * gv0 + i);
    }
    asm volatile("cp.async.commit_group;" ::: "memory");
}

__global__ __launch_bounds__(BLOCK, 4)
void lbs_hmma_kernel(const float* __restrict__ points,
                     const float* __restrict__ weights,
                     const float* __restrict__ se3,
                     float* __restrict__ out,
                     int N, int n_tiles)
{
    // A tile [128][64] fp16 swizzled; per-warp 32-row region doubles as D-exchange
    __shared__ __align__(1024) __half s_A[TILE_M * 64];     // 16 KB
    // B build area (hi/lo SE3); after frags hoisted to regs, reused as points bufs
    __shared__ __align__(1024) char  s_BP[4096];            // 4 KB
    __shared__ __align__(16)   float s_lin[4][32 * NJ];     // 28.16 KB fp32 slabs

    const int tid  = threadIdx.x;
    const int wid  = tid >> 5;
    const int lane = tid & 31;

    const uint32_t a_base = smem_u32(s_A);

    // ---- build B (hi/lo split of SE3 rows 0..2, n = r*4+c), hoist frags, free area ----
    uint32_t BH[4][4], BL[4][4];
    {
        __half* b0 = (__half*)s_BP;               // [16][64]
        __half* b1 = (__half*)(s_BP + 2048);
        for (int idx = tid; idx < 16 * 64; idx += BLOCK) {
            int n = idx >> 6;
            int k = idx & 63;
            float v = (k < NJ && n < 12) ? se3[k * 16 + n] : 0.0f;
            __half hh = __float2half_rn(v);
            __half hl = __float2half_rn(v - __half2float(hh));
            uint32_t off = (uint32_t)(n * 128 + 2 * k);
            off ^= ((off >> 3) & 0x70);
            *(__half*)((char*)b0 + off) = hh;
            *(__half*)((char*)b1 + off) = hl;
        }
        __syncthreads();
        const uint32_t b0b = smem_u32(b0), b1b = smem_u32(b1);
        int nrow = (lane & 7) + (((lane >> 4) & 1) << 3);
        #pragma unroll
        for (int chunk = 0; chunk < 4; chunk++) {
            uint32_t c = (uint32_t)(chunk * 32) + (((uint32_t)(lane >> 3) & 1) << 4);
            uint32_t boff = (uint32_t)nrow * 128 + (c ^ ((uint32_t)(nrow & 7) << 4));
            ldsm_x4(BH[chunk], b0b + boff);
            ldsm_x4(BL[chunk], b1b + boff);
        }
        __syncthreads();   // frags read; s_BP now free for points buffers
    }

    float* slabw = s_lin[wid];
    float* ptsb[2] = { (float*)(s_BP + wid * 1024),
                       (float*)(s_BP + wid * 1024 + 512) };

    // ---- prologue: prefetch tile0's slab + points ----
    int tile = blockIdx.x;
    int it = 0;
    if (tile < n_tiles)
        stage_tile(weights, points, slabw, ptsb[0],
                   (long)tile * TILE_M + wid * 32, N, lane);

    for (; tile < n_tiles; tile += gridDim.x, it++) {
        const long gv0 = (long)tile * TILE_M + wid * 32;
        const float* ptsw = ptsb[it & 1];

        // ---- wait this tile's data, pull own row into packed fp16 regs ----
        asm volatile("cp.async.wait_group 0;" ::: "memory");
        __syncwarp();

        uint32_t h[28];
        {
            const float* rp = slabw + lane * NJ;
            #pragma unroll
            for (int q = 0; q < 27; q++)
                h[q] = packh2(rp[2 * q], rp[2 * q + 1]);
            h[27] = packh2(rp[54], 0.0f);
        }
        __syncwarp();   // all slab reads done before reissue

        // ---- issue prefetch for next tile (slab + points) ----
        {
            long nt = (long)tile + gridDim.x;
            if (nt < n_tiles)
                stage_tile(weights, points, slabw, ptsb[(it + 1) & 1],
                           nt * TILE_M + wid * 32, N, lane);
            else
                asm volatile("cp.async.commit_group;" ::: "memory");
        }

        // ---- repack regs -> swizzled A tile (K zero-padded to 64) ----
        {
            const uint32_t rowbase = a_base + (uint32_t)(wid * 32 + lane) * 128;
            const uint32_t xr = (uint32_t)(lane & 7) << 4;
            #pragma unroll
            for (int b = 0; b < 8; b++) {
                uint32_t h0 = (4 * b + 0 < 28) ? h[4 * b + 0] : 0u;
                uint32_t h1 = (4 * b + 1 < 28) ? h[4 * b + 1] : 0u;
                uint32_t h2 = (4 * b + 2 < 28) ? h[4 * b + 2] : 0u;
                uint32_t h3 = (4 * b + 3 < 28) ? h[4 * b + 3] : 0u;
                uint32_t ad = rowbase + (((uint32_t)(b * 16)) ^ xr);
                asm volatile("st.shared.v4.b32 [%0], {%1,%2,%3,%4};"
                             :: "r"(ad), "r"(h0), "r"(h1), "r"(h2), "r"(h3) : "memory");
            }
        }
        __syncwarp();

        // ---- MMA: D[32x16] = A_warp[32x64] * (Bh + Bl)^T, B from registers ----
        float d[4][4];
        #pragma unroll
        for (int i = 0; i < 4; i++)
            #pragma unroll
            for (int q = 0; q < 4; q++) d[i][q] = 0.0f;

        #pragma unroll
        for (int chunk = 0; chunk < 4; chunk++) {
            uint32_t a0[4], a1[4];
            {
                int rowa = wid * 32 + (lane & 15);
                uint32_t c = (uint32_t)(chunk * 32) + (((uint32_t)lane >> 4) << 4);
                uint32_t ad = a_base + (uint32_t)rowa * 128 + (c ^ ((uint32_t)(rowa & 7) << 4));
                ldsm_x4(a0, ad);
                ldsm_x4(a1, ad + 16 * 128);
            }
            mma16816(d[0], a0, BH[chunk][0], BH[chunk][1]);
            mma16816(d[1], a0, BH[chunk][2], BH[chunk][3]);
            mma16816(d[2], a1, BH[chunk][0], BH[chunk][1]);
            mma16816(d[3], a1, BH[chunk][2], BH[chunk][3]);
            mma16816(d[0], a0, BL[chunk][0], BL[chunk][1]);
            mma16816(d[1], a0, BL[chunk][2], BL[chunk][3]);
            mma16816(d[2], a1, BL[chunk][0], BL[chunk][1]);
            mma16816(d[3], a1, BL[chunk][2], BL[chunk][3]);
        }

        // ---- D exchange through the (now dead) A region, swizzled ----
        char* awarp = (char*)s_A + (wid * 32) * 128;
        {
            int r0 = lane >> 2;
            int cq = 2 * (lane & 3);
            #pragma unroll
            for (int mt = 0; mt < 2; mt++) {
                #pragma unroll
                for (int nt = 0; nt < 2; nt++) {
                    float* dd = d[mt * 2 + nt];
                    int rr = mt * 16 + r0;
                    uint32_t cb = (uint32_t)(nt * 8 + cq) * 4;
                    *(float2*)(awarp + rr * 128 + swb(cb, rr))
                        = make_float2(dd[0], dd[1]);
                    *(float2*)(awarp + (rr + 8) * 128 + swb(cb, rr + 8))
                        = make_float2(dd[2], dd[3]);
                }
            }
        }
        __syncwarp();

        // ---- epilogue: out = A3x4 * [p;1], points from smem ----
        long v = gv0 + lane;
        if (v < N) {
            float4 q0 = *(float4*)(awarp + lane * 128 + swb(0u,  lane));
            float4 q1 = *(float4*)(awarp + lane * 128 + swb(16u, lane));
            float4 q2 = *(float4*)(awarp + lane * 128 + swb(32u, lane));
            const float* pp = ptsw + 3 * lane;
            float px = pp[0], py = pp[1], pz = pp[2];
            out[3 * v + 0] = fmaf(q0.x, px, fmaf(q0.y, py, fmaf(q0.z, pz, q0.w)));
            out[3 * v + 1] = fmaf(q1.x, px, fmaf(q1.y, py, fmaf(q1.z, pz, q1.w)));
            out[3 * v + 2] = fmaf(q2.x, px, fmaf(q2.y, py, fmaf(q2.z, pz, q2.w)));
        }
        __syncwarp();   // exchange reads done before next iter's repack overwrites A
    }
}

extern "C" void kernel_launch(void* const* d_in, const int* in_sizes, int n_in,
                              void* d_out, int out_size)
{
    const int N = out_size / 3;
    const float* points = nullptr;
    const float* weights = nullptr;
    const float* se3 = nullptr;

    for (int i = 0; i < n_in; i++) {
        long sz = in_sizes[i];
        if (sz == (long)NJ * 16)      se3 = (const float*)d_in[i];
        else if (sz == (long)N * NJ)  weights = (const float*)d_in[i];
        else if (sz == (long)N * 3)   points = (const float*)d_in[i];
    }

    int n_tiles = (N + TILE_M - 1) / TILE_M;
    int grid = n_tiles < GRID_P ? n_tiles : GRID_P;
    lbs_hmma_kernel<<<grid, BLOCK>>>(points, weights, se3, (float*)d_out, N, n_tiles);
}